// round 3
// baseline (speedup 1.0000x reference)
#include <cuda_runtime.h>
#include <cstdint>

// ---------------------------------------------------------------------------
// CrossModalAttention: 6 strided GEMMs on TF32 warp-MMA + softmax + concat.
// B=8, CQ=CKV=E=256, Nq=4096, Nkv=1024.
// ---------------------------------------------------------------------------

#define BM 128
#define BN 128
#define BK 16
#define SPAD 132   // row stride (mod 32 == 4) -> conflict-free fragment loads

// Scratch (device globals; no allocation allowed)
__device__ float g_theta[(size_t)8 * 256 * 4096];   // [B,E,Nq]
__device__ float g_phi  [(size_t)8 * 256 * 1024];   // [B,E,Nkv]
__device__ float g_gv   [(size_t)8 * 256 * 1024];   // [B,E,Nkv]
__device__ float g_attn [(size_t)8 * 4096 * 1024];  // [B,Nq,Nkv]
__device__ float g_obuf [(size_t)8 * 256 * 4096];   // [B,E,Nq]

__device__ __forceinline__ uint32_t f2tf32(float x) {
    uint32_t u;
    asm("cvt.rna.tf32.f32 %0, %1;" : "=r"(u) : "f"(x));
    return u;
}

__device__ __forceinline__ void mma_tf32(
    float& c0, float& c1, float& c2, float& c3,
    uint32_t a0, uint32_t a1, uint32_t a2, uint32_t a3,
    uint32_t b0, uint32_t b1)
{
    asm volatile(
        "mma.sync.aligned.m16n8k8.row.col.f32.tf32.tf32.f32 "
        "{%0,%1,%2,%3}, {%4,%5,%6,%7}, {%8,%9}, {%0,%1,%2,%3};"
        : "+f"(c0), "+f"(c1), "+f"(c2), "+f"(c3)
        : "r"(a0), "r"(a1), "r"(a2), "r"(a3), "r"(b0), "r"(b1));
}

// Generic strided batched GEMM on TF32 tensor cores.
// C[m,n] = alpha * sum_k A[m,k]*B[k,n]
// A elem: A + z*aB + m*am + k*ak ; B: B + z*bB + k*bk + n*bn ;
// C: C + z*cB + m*cm + n (n contiguous). M,N mult of 128, K mult of 16.
__global__ __launch_bounds__(256, 2) void gemm_tf32_kernel(
    const float* __restrict__ A, const float* __restrict__ B,
    float* __restrict__ C,
    int K,
    long aB, long bB, long cB,
    int am, int ak, int bk, int bn, int cm, float alpha)
{
    __shared__ uint32_t As[BK][SPAD];
    __shared__ uint32_t Bs[BK][SPAD];

    const float* Ab = A + (long)blockIdx.z * aB;
    const float* Bb = B + (long)blockIdx.z * bB;
    float*       Cb = C + (long)blockIdx.z * cB;

    const int m0 = blockIdx.y * BM;
    const int n0 = blockIdx.x * BN;
    const int tid  = threadIdx.x;
    const int warp = tid >> 5;
    const int lane = tid & 31;
    const int wm = warp & 1;          // 2 warps along M (64 rows each)
    const int wn = warp >> 1;         // 4 warps along N (32 cols each)
    const int tg  = lane & 3;         // thread-in-group
    const int gid = lane >> 2;        // group id (0..7)

    const bool aKfast = (ak == 1);
    const bool bKfast = (bk == 1);

    // Precompute per-thread load offsets and smem store indices (8 each).
    int offA[8], offB[8], sA[8], sB[8];
    #pragma unroll
    for (int l = 0; l < 8; l++) {
        int idx = tid + l * 256;
        int m, k;
        if (aKfast) { k = idx & 15; m = idx >> 4; }
        else        { m = idx & 127; k = idx >> 7; }
        offA[l] = (m0 + m) * am + k * ak;
        sA[l] = k * SPAD + m;
        int n, k2;
        if (bKfast) { k2 = idx & 15; n = idx >> 4; }
        else        { n = idx & 127; k2 = idx >> 7; }
        offB[l] = k2 * bk + (n0 + n) * bn;
        sB[l] = k2 * SPAD + n;
    }

    float acc[4][4][4];
    #pragma unroll
    for (int i = 0; i < 4; i++)
        #pragma unroll
        for (int j = 0; j < 4; j++)
            #pragma unroll
            for (int r = 0; r < 4; r++) acc[i][j][r] = 0.0f;

    float pa[8], pb[8];
    // Prefetch tile 0
    #pragma unroll
    for (int l = 0; l < 8; l++) { pa[l] = Ab[offA[l]]; pb[l] = Bb[offB[l]]; }

    uint32_t* AsF = &As[0][0];
    uint32_t* BsF = &Bs[0][0];

    int kt = 0;
    for (;;) {
        __syncthreads();
        #pragma unroll
        for (int l = 0; l < 8; l++) {
            AsF[sA[l]] = f2tf32(pa[l]);
            BsF[sB[l]] = f2tf32(pb[l]);
        }
        __syncthreads();

        kt += BK;
        const bool more = (kt < K);
        if (more) {
            const int da = kt * ak, db = kt * bk;
            #pragma unroll
            for (int l = 0; l < 8; l++) {
                pa[l] = Ab[offA[l] + da];
                pb[l] = Bb[offB[l] + db];
            }
        }

        // Compute 2 k-substeps of 8
        #pragma unroll
        for (int ks = 0; ks < BK; ks += 8) {
            uint32_t af[4][4], bf[4][2];
            #pragma unroll
            for (int mt = 0; mt < 4; mt++) {
                const int mb = wm * 64 + mt * 16 + gid;
                af[mt][0] = As[ks + tg    ][mb    ];
                af[mt][1] = As[ks + tg    ][mb + 8];
                af[mt][2] = As[ks + tg + 4][mb    ];
                af[mt][3] = As[ks + tg + 4][mb + 8];
            }
            #pragma unroll
            for (int nt = 0; nt < 4; nt++) {
                const int nb = wn * 32 + nt * 8 + gid;
                bf[nt][0] = Bs[ks + tg    ][nb];
                bf[nt][1] = Bs[ks + tg + 4][nb];
            }
            #pragma unroll
            for (int mt = 0; mt < 4; mt++)
                #pragma unroll
                for (int nt = 0; nt < 4; nt++)
                    mma_tf32(acc[mt][nt][0], acc[mt][nt][1],
                             acc[mt][nt][2], acc[mt][nt][3],
                             af[mt][0], af[mt][1], af[mt][2], af[mt][3],
                             bf[nt][0], bf[nt][1]);
        }
        if (!more) break;
    }

    // Epilogue
    #pragma unroll
    for (int mt = 0; mt < 4; mt++) {
        const int row = m0 + wm * 64 + mt * 16 + gid;
        #pragma unroll
        for (int nt = 0; nt < 4; nt++) {
            const int col = n0 + wn * 32 + nt * 8 + tg * 2;
            float2 v0 = make_float2(acc[mt][nt][0] * alpha, acc[mt][nt][1] * alpha);
            float2 v1 = make_float2(acc[mt][nt][2] * alpha, acc[mt][nt][3] * alpha);
            *(float2*)&Cb[(long)row * cm + col]       = v0;
            *(float2*)&Cb[(long)(row + 8) * cm + col] = v1;
        }
    }
}

// Row softmax over contiguous rows of length 1024. One block per row.
__global__ __launch_bounds__(256) void softmax_kernel(float* __restrict__ S)
{
    float4* row = (float4*)(S + (long)blockIdx.x * 1024);
    const int tid = threadIdx.x;
    float4 v = row[tid];

    float m = fmaxf(fmaxf(v.x, v.y), fmaxf(v.z, v.w));
    #pragma unroll
    for (int o = 16; o; o >>= 1) m = fmaxf(m, __shfl_xor_sync(0xffffffffu, m, o));

    __shared__ float smax[8];
    __shared__ float ssum[8];
    if ((tid & 31) == 0) smax[tid >> 5] = m;
    __syncthreads();
    m = smax[0];
    #pragma unroll
    for (int i = 1; i < 8; i++) m = fmaxf(m, smax[i]);

    v.x = __expf(v.x - m); v.y = __expf(v.y - m);
    v.z = __expf(v.z - m); v.w = __expf(v.w - m);
    float s = v.x + v.y + v.z + v.w;
    #pragma unroll
    for (int o = 16; o; o >>= 1) s += __shfl_xor_sync(0xffffffffu, s, o);
    if ((tid & 31) == 0) ssum[tid >> 5] = s;
    __syncthreads();
    s = ssum[0];
    #pragma unroll
    for (int i = 1; i < 8; i++) s += ssum[i];

    const float inv = 1.0f / s;
    v.x *= inv; v.y *= inv; v.z *= inv; v.w *= inv;
    row[tid] = v;
}

// Copy C [B,256,4096] into first half of out [B,512,4096] (float4 units).
__global__ __launch_bounds__(256) void copy_c_kernel(
    const float4* __restrict__ src, float4* __restrict__ dst)
{
    long i = (long)blockIdx.x * 256 + threadIdx.x;   // 8 * 262144 total
    long b = i >> 18;
    long off = i & 262143;
    dst[b * 524288 + off] = src[i];
}

extern "C" void kernel_launch(void* const* d_in, const int* in_sizes, int n_in,
                              void* d_out, int out_size)
{
    const float* C   = (const float*)d_in[0];   // [8,256,64,64]
    const float* P   = (const float*)d_in[1];   // [8,256,32,32]
    const float* thw = (const float*)d_in[2];   // [256,256]
    const float* phw = (const float*)d_in[3];   // [256,256]
    const float* gw  = (const float*)d_in[4];   // [256,256]
    const float* ow  = (const float*)d_in[5];   // [256,256]
    float* out = (float*)d_out;                 // [8,512,64,64]

    float *theta, *phi, *gv, *attn, *obuf;
    cudaGetSymbolAddress((void**)&theta, g_theta);
    cudaGetSymbolAddress((void**)&phi,   g_phi);
    cudaGetSymbolAddress((void**)&gv,    g_gv);
    cudaGetSymbolAddress((void**)&attn,  g_attn);
    cudaGetSymbolAddress((void**)&obuf,  g_obuf);

    const dim3 blk(256);
    const long NQ = 4096, NKV = 1024, E = 256;

    // 1) theta = theta_w[E,CQ] @ C[b][CQ,Nq]   -> [B,E,Nq]
    gemm_tf32_kernel<<<dim3(32, 2, 8), blk>>>(thw, C, theta, 256,
        0, E * NQ, E * NQ,
        /*am*/256, /*ak*/1, /*bk*/4096, /*bn*/1, /*cm*/4096, 1.0f);

    // 2) phi = phi_w @ P[b] ; 3) gv = g_w @ P[b]  -> [B,E,Nkv]
    gemm_tf32_kernel<<<dim3(8, 2, 8), blk>>>(phw, P, phi, 256,
        0, E * NKV, E * NKV, 256, 1, 1024, 1, 1024, 1.0f);
    gemm_tf32_kernel<<<dim3(8, 2, 8), blk>>>(gw, P, gv, 256,
        0, E * NKV, E * NKV, 256, 1, 1024, 1, 1024, 1.0f);

    // 4) S[n,m] = sum_e theta[e,n]*phi[e,m] / 16   -> [B,Nq,Nkv]
    gemm_tf32_kernel<<<dim3(8, 32, 8), blk>>>(theta, phi, attn, 256,
        E * NQ, E * NKV, NQ * NKV,
        /*am*/1, /*ak*/4096, /*bk*/1024, /*bn*/1, /*cm*/1024, 0.0625f);

    // 5) softmax over each row of 1024
    softmax_kernel<<<8 * 4096, blk>>>(attn);

    // 6) O[e,n] = sum_m gv[e,m]*attn[n,m]   -> [B,E,Nq]
    gemm_tf32_kernel<<<dim3(32, 2, 8), blk>>>(gv, attn, obuf, 1024,
        E * NKV, NQ * NKV, E * NQ,
        /*am*/1024, /*ak*/1, /*bk*/1, /*bn*/1024, /*cm*/4096, 1.0f);

    // 7) F = out_w @ O[b] -> second half of out (channels 256..511)
    gemm_tf32_kernel<<<dim3(32, 2, 8), blk>>>(ow, obuf, out + 256L * 4096, 256,
        0, E * NQ, 512L * 4096,
        /*am*/256, /*ak*/1, /*bk*/4096, /*bn*/1, /*cm*/4096, 1.0f);

    // 8) concat: copy C into first half of out
    copy_c_kernel<<<8192, blk>>>((const float4*)C, (float4*)out);
}

// round 5
// speedup vs baseline: 2.1998x; 2.1998x over previous
#include <cuda_runtime.h>
#include <cuda_bf16.h>
#include <cstdint>

typedef __nv_bfloat16 bf16;

// ---------------------------------------------------------------------------
// CrossModalAttention, sm_100 warp-MMA path:
// bf16 m16n8k16 mma.sync + ldmatrix + cp.async 3-stage pipeline.
// All GEMMs: D[m,n] = alpha * sum_k A[m,k]*B[n,k], A/B bf16 K-contiguous.
// ---------------------------------------------------------------------------

// Scratch (device globals; allocation-free)
__device__ bf16  g_w16   [4][65536];                 // thw, phw, gw, ow in bf16
__device__ bf16  g_CTb   [(size_t)8 * 4096 * 256];   // [B][Nq][CQ]
__device__ bf16  g_PTb   [(size_t)8 * 1024 * 256];   // [B][Nkv][CKV]
__device__ bf16  g_thetaT[(size_t)8 * 4096 * 256];   // [B][Nq][E]
__device__ bf16  g_phiT  [(size_t)8 * 1024 * 256];   // [B][Nkv][E]
__device__ bf16  g_gv    [(size_t)8 * 256 * 1024];   // [B][E][Nkv]
__device__ float g_attn  [(size_t)8 * 4096 * 1024];  // [B][Nq][Nkv] logits f32
__device__ bf16  g_attnb [(size_t)8 * 4096 * 1024];  // [B][Nq][Nkv] weights bf16
__device__ bf16  g_obufT [(size_t)8 * 4096 * 256];   // [B][Nq][E]

#define SWZ(x) ((x) ^ (((x) >> 3) & 0x70))

__device__ __forceinline__ uint32_t smem_u32(const void* p) {
    uint32_t a;
    asm("{ .reg .u64 t; cvta.to.shared.u64 t, %1; cvt.u32.u64 %0, t; }" : "=r"(a) : "l"(p));
    return a;
}
__device__ __forceinline__ void cp16(uint32_t dst, const void* src) {
    asm volatile("cp.async.cg.shared.global [%0], [%1], 16;" :: "r"(dst), "l"(src) : "memory");
}
__device__ __forceinline__ void ldsm4(uint32_t* r, uint32_t a) {
    asm volatile("ldmatrix.sync.aligned.m8n8.x4.shared.b16 {%0,%1,%2,%3}, [%4];"
        : "=r"(r[0]), "=r"(r[1]), "=r"(r[2]), "=r"(r[3]) : "r"(a));
}
__device__ __forceinline__ void mma_bf16(float* c, const uint32_t* a, uint32_t b0, uint32_t b1) {
    asm volatile(
        "mma.sync.aligned.m16n8k16.row.col.f32.bf16.bf16.f32 "
        "{%0,%1,%2,%3},{%4,%5,%6,%7},{%8,%9},{%0,%1,%2,%3};"
        : "+f"(c[0]), "+f"(c[1]), "+f"(c[2]), "+f"(c[3])
        : "r"(a[0]), "r"(a[1]), "r"(a[2]), "r"(a[3]), "r"(b0), "r"(b1));
}

// 128x128x(BK=64) tile, 8 warps (2m x 4n), warp tile 64x32, 3-stage cp.async.
// A: z*aB + m*as + k    B: z*bB + n*bs + k (bf16, k contiguous)
// Out: normal [m][n] (ldO = row stride, n contig) or transposed [n][m].
__global__ __launch_bounds__(256) void gemm_bf16_kernel(
    const bf16* __restrict__ A, const bf16* __restrict__ B, void* __restrict__ Out,
    int K, int as, long aB, int bs, long bB, long oB, int ldO,
    int transOut, int outBf16, float alpha)
{
    extern __shared__ char smem[];
    const uint32_t sb = smem_u32(smem);
    const int tid = threadIdx.x, warp = tid >> 5, lane = tid & 31;
    const int m0 = blockIdx.x * 128, n0 = blockIdx.y * 128;
    const bf16* Ab = A + (long)blockIdx.z * aB + (long)m0 * as;
    const bf16* Bb = B + (long)blockIdx.z * bB + (long)n0 * bs;

    // copy geometry: per operand 128 rows x 8 chunks(16B); 4 chunks/thread
    int crow[4], ckc[4]; uint32_t cdst[4];
    #pragma unroll
    for (int j = 0; j < 4; j++) {
        int idx = tid + j * 256;
        crow[j] = idx >> 3; ckc[j] = idx & 7;
        cdst[j] = SWZ((uint32_t)(crow[j] * 128 + ckc[j] * 16));
    }

    const int nk = K >> 6;

    #define ISSUE(IT) do {                                                    \
        int _kt = (IT) * 64;                                                  \
        uint32_t _sA = sb + ((IT) % 3) * 32768, _sB = _sA + 16384;            \
        _Pragma("unroll")                                                     \
        for (int j = 0; j < 4; j++) {                                         \
            cp16(_sA + cdst[j], Ab + (long)crow[j] * as + _kt + ckc[j] * 8);  \
            cp16(_sB + cdst[j], Bb + (long)crow[j] * bs + _kt + ckc[j] * 8);  \
        }                                                                     \
    } while (0)

    #pragma unroll
    for (int s = 0; s < 2; s++) {
        if (s < nk) ISSUE(s);
        asm volatile("cp.async.commit_group;" ::: "memory");
    }

    float acc[4][4][4];
    #pragma unroll
    for (int i = 0; i < 4; i++)
        #pragma unroll
        for (int j = 0; j < 4; j++)
            #pragma unroll
            for (int r = 0; r < 4; r++) acc[i][j][r] = 0.0f;

    const int wm = warp & 1, wn = warp >> 1;
    const int arow = lane & 15;
    const int ksel = (lane >> 4) * 16;   // byte offset selecting k-half

    for (int it = 0; it < nk; it++) {
        if (it + 2 < nk) ISSUE(it + 2);
        asm volatile("cp.async.commit_group;" ::: "memory");
        asm volatile("cp.async.wait_group 2;" ::: "memory");
        __syncthreads();

        const uint32_t sA = sb + (it % 3) * 32768, sB = sA + 16384;
        #pragma unroll
        for (int ks = 0; ks < 64; ks += 16) {
            uint32_t af[4][4], bfr[2][4];
            #pragma unroll
            for (int mt = 0; mt < 4; mt++)
                ldsm4(af[mt], sA + SWZ((uint32_t)((wm * 64 + mt * 16 + arow) * 128 + ks * 2 + ksel)));
            #pragma unroll
            for (int h = 0; h < 2; h++)
                ldsm4(bfr[h], sB + SWZ((uint32_t)((wn * 32 + h * 16 + arow) * 128 + ks * 2 + ksel)));
            #pragma unroll
            for (int mt = 0; mt < 4; mt++)
                #pragma unroll
                for (int nt = 0; nt < 4; nt++)
                    mma_bf16(acc[mt][nt], af[mt],
                             bfr[nt >> 1][nt & 1], bfr[nt >> 1][(nt & 1) + 2]);
        }
        __syncthreads();
    }

    // Epilogue
    const int gid = lane >> 2, tg = lane & 3;
    const long zo = (long)blockIdx.z * oB;
    #pragma unroll
    for (int mt = 0; mt < 4; mt++) {
        const int row = m0 + wm * 64 + mt * 16 + gid;
        #pragma unroll
        for (int nt = 0; nt < 4; nt++) {
            const int col = n0 + wn * 32 + nt * 8 + tg * 2;
            float v0 = acc[mt][nt][0] * alpha, v1 = acc[mt][nt][1] * alpha;
            float v2 = acc[mt][nt][2] * alpha, v3 = acc[mt][nt][3] * alpha;
            if (transOut) {           // bf16, Out[n][m]
                bf16* O = (bf16*)Out + zo;
                O[(long)col * ldO + row]           = __float2bfloat16(v0);
                O[(long)(col + 1) * ldO + row]     = __float2bfloat16(v1);
                O[(long)col * ldO + row + 8]       = __float2bfloat16(v2);
                O[(long)(col + 1) * ldO + row + 8] = __float2bfloat16(v3);
            } else if (outBf16) {     // bf16, Out[m][n]
                bf16* O = (bf16*)Out + zo;
                *(__nv_bfloat162*)&O[(long)row * ldO + col]       = __floats2bfloat162_rn(v0, v1);
                *(__nv_bfloat162*)&O[(long)(row + 8) * ldO + col] = __floats2bfloat162_rn(v2, v3);
            } else {                  // f32, Out[m][n]
                float* O = (float*)Out + zo;
                *(float2*)&O[(long)row * ldO + col]       = make_float2(v0, v1);
                *(float2*)&O[(long)(row + 8) * ldO + col] = make_float2(v2, v3);
            }
        }
    }
}

// Transpose+convert: f32 [Z][256][Cc] -> bf16 [Z][Cc][256]
__global__ __launch_bounds__(256) void transcvt_kernel(
    const float* __restrict__ in, bf16* __restrict__ out, int Cc)
{
    __shared__ float t[32][33];
    const long base = (long)blockIdx.z * 256 * Cc;
    const int c0 = blockIdx.x * 32, r0 = blockIdx.y * 32;
    const int tx = threadIdx.x, ty = threadIdx.y;
    #pragma unroll
    for (int i = 0; i < 4; i++)
        t[ty + i * 8][tx] = in[base + (long)(r0 + ty + i * 8) * Cc + c0 + tx];
    __syncthreads();
    #pragma unroll
    for (int i = 0; i < 4; i++)
        out[base + (long)(c0 + ty + i * 8) * 256 + r0 + tx] = __float2bfloat16(t[tx][ty + i * 8]);
}

// Elementwise f32 -> bf16 (weights)
__global__ __launch_bounds__(256) void cvt_kernel(
    const float* __restrict__ in, bf16* __restrict__ out)
{
    int i = blockIdx.x * 256 + threadIdx.x;
    out[i] = __float2bfloat16(in[i]);
}

// Row softmax (len 1024): read f32 logits, write bf16 weights.
__global__ __launch_bounds__(256) void softmax_kernel(
    const float* __restrict__ S, __nv_bfloat162* __restrict__ Sb)
{
    const float4* row = (const float4*)(S + (long)blockIdx.x * 1024);
    __nv_bfloat162* rowb = Sb + (long)blockIdx.x * 512;
    const int tid = threadIdx.x;
    float4 v = row[tid];
    float m = fmaxf(fmaxf(v.x, v.y), fmaxf(v.z, v.w));
    #pragma unroll
    for (int o = 16; o; o >>= 1) m = fmaxf(m, __shfl_xor_sync(0xffffffffu, m, o));
    __shared__ float smax[8], ssum[8];
    if ((tid & 31) == 0) smax[tid >> 5] = m;
    __syncthreads();
    m = smax[0];
    #pragma unroll
    for (int i = 1; i < 8; i++) m = fmaxf(m, smax[i]);
    v.x = __expf(v.x - m); v.y = __expf(v.y - m);
    v.z = __expf(v.z - m); v.w = __expf(v.w - m);
    float s = v.x + v.y + v.z + v.w;
    #pragma unroll
    for (int o = 16; o; o >>= 1) s += __shfl_xor_sync(0xffffffffu, s, o);
    if ((tid & 31) == 0) ssum[tid >> 5] = s;
    __syncthreads();
    s = ssum[0];
    #pragma unroll
    for (int i = 1; i < 8; i++) s += ssum[i];
    const float inv = 1.0f / s;
    rowb[tid * 2]     = __floats2bfloat162_rn(v.x * inv, v.y * inv);
    rowb[tid * 2 + 1] = __floats2bfloat162_rn(v.z * inv, v.w * inv);
}

__global__ __launch_bounds__(256) void copy_c_kernel(
    const float4* __restrict__ src, float4* __restrict__ dst)
{
    long i = (long)blockIdx.x * 256 + threadIdx.x;
    long b = i >> 18;
    long off = i & 262143;
    dst[b * 524288 + off] = src[i];
}

extern "C" void kernel_launch(void* const* d_in, const int* in_sizes, int n_in,
                              void* d_out, int out_size)
{
    const float* C   = (const float*)d_in[0];
    const float* P   = (const float*)d_in[1];
    const float* thw = (const float*)d_in[2];
    const float* phw = (const float*)d_in[3];
    const float* gw  = (const float*)d_in[4];
    const float* ow  = (const float*)d_in[5];
    float* out = (float*)d_out;

    bf16 *w16, *CTb, *PTb, *thetaT, *phiT, *gv, *attnb, *obufT;
    float* attn;
    cudaGetSymbolAddress((void**)&w16, g_w16);
    cudaGetSymbolAddress((void**)&CTb, g_CTb);
    cudaGetSymbolAddress((void**)&PTb, g_PTb);
    cudaGetSymbolAddress((void**)&thetaT, g_thetaT);
    cudaGetSymbolAddress((void**)&phiT, g_phiT);
    cudaGetSymbolAddress((void**)&gv, g_gv);
    cudaGetSymbolAddress((void**)&attn, g_attn);
    cudaGetSymbolAddress((void**)&attnb, g_attnb);
    cudaGetSymbolAddress((void**)&obufT, g_obufT);

    static int smem_set = 0;
    if (!smem_set) {
        cudaFuncSetAttribute(gemm_bf16_kernel,
                             cudaFuncAttributeMaxDynamicSharedMemorySize, 98304);
        smem_set = 1;
    }

    const dim3 blk(256);
    const long NQ = 4096, NKV = 1024;

    // Convert weights + transpose-convert inputs to bf16 K-major
    cvt_kernel<<<256, blk>>>(thw, w16);
    cvt_kernel<<<256, blk>>>(phw, w16 + 65536);
    cvt_kernel<<<256, blk>>>(gw,  w16 + 2 * 65536);
    cvt_kernel<<<256, blk>>>(ow,  w16 + 3 * 65536);
    transcvt_kernel<<<dim3(128, 8, 8), dim3(32, 8)>>>(C, CTb, 4096);
    transcvt_kernel<<<dim3(32, 8, 8), dim3(32, 8)>>>(P, PTb, 1024);

    // 1) thetaT[nq][e] = thw @ C   (transposed bf16 out)
    gemm_bf16_kernel<<<dim3(2, 32, 8), blk, 98304>>>(w16, CTb, thetaT, 256,
        256, 0, 256, NQ * 256, NQ * 256, 256, 1, 1, 1.0f);
    // 2) phiT[nkv][e] = phw @ P
    gemm_bf16_kernel<<<dim3(2, 8, 8), blk, 98304>>>(w16 + 65536, PTb, phiT, 256,
        256, 0, 256, NKV * 256, NKV * 256, 256, 1, 1, 1.0f);
    // 3) gv[e][nkv] = gw @ P       (normal bf16 out)
    gemm_bf16_kernel<<<dim3(2, 8, 8), blk, 98304>>>(w16 + 2 * 65536, PTb, gv, 256,
        256, 0, 256, NKV * 256, 256 * NKV, 1024, 0, 1, 1.0f);
    // 4) attn[nq][nkv] = thetaT . phiT / 16   (f32 logits)
    gemm_bf16_kernel<<<dim3(32, 8, 8), blk, 98304>>>(thetaT, phiT, attn, 256,
        256, NQ * 256, 256, NKV * 256, NQ * NKV, 1024, 0, 0, 0.0625f);
    // 5) softmax -> bf16 weights
    softmax_kernel<<<8 * 4096, blk>>>(attn, (__nv_bfloat162*)attnb);
    // 6) obufT[nq][e] = gv . attnb  (transposed bf16 out), K=1024
    gemm_bf16_kernel<<<dim3(2, 32, 8), blk, 98304>>>(gv, attnb, obufT, 1024,
        1024, 256 * NKV, 1024, NQ * NKV, NQ * 256, 256, 1, 1, 1.0f);
    // 7) out2[c][nq] = ow . obufT   (f32 out into second half)
    gemm_bf16_kernel<<<dim3(2, 32, 8), blk, 98304>>>(w16 + 3 * 65536, obufT,
        out + 256L * 4096, 256,
        256, 0, 256, NQ * 256, 512L * 4096, 4096, 0, 0, 1.0f);
    // 8) concat copy
    copy_c_kernel<<<8192, blk>>>((const float4*)C, (float4*)out);
}

// round 6
// speedup vs baseline: 2.4351x; 1.1070x over previous
#include <cuda_runtime.h>
#include <cuda_bf16.h>
#include <cstdint>

typedef __nv_bfloat16 bf16;

// ---------------------------------------------------------------------------
// CrossModalAttention, sm_100:
//   stages 1-3,7: bf16 m16n8k16 mma.sync GEMM (ldmatrix + cp.async, 3-stage)
//   stages 4-6  : fused flash-attention kernel (online softmax, no attn matrix)
// ---------------------------------------------------------------------------

// Scratch (device globals; allocation-free)
__device__ bf16  g_w16   [4][65536];                 // thw, phw, gw, ow in bf16
__device__ bf16  g_CTb   [(size_t)8 * 4096 * 256];   // [B][Nq][CQ]
__device__ bf16  g_PTb   [(size_t)8 * 1024 * 256];   // [B][Nkv][CKV]
__device__ bf16  g_thetaT[(size_t)8 * 4096 * 256];   // [B][Nq][E]  (pre-scaled 1/16)
__device__ bf16  g_phiT  [(size_t)8 * 1024 * 256];   // [B][Nkv][E]
__device__ bf16  g_gv    [(size_t)8 * 256 * 1024];   // [B][E][Nkv]
__device__ bf16  g_obufT [(size_t)8 * 4096 * 256];   // [B][Nq][E]

#define SWZ(x) ((x) ^ (((x) >> 3) & 0x70))

__device__ __forceinline__ uint32_t smem_u32(const void* p) {
    uint32_t a;
    asm("{ .reg .u64 t; cvta.to.shared.u64 t, %1; cvt.u32.u64 %0, t; }" : "=r"(a) : "l"(p));
    return a;
}
__device__ __forceinline__ void cp16(uint32_t dst, const void* src) {
    asm volatile("cp.async.cg.shared.global [%0], [%1], 16;" :: "r"(dst), "l"(src) : "memory");
}
__device__ __forceinline__ void ldsm4(uint32_t* r, uint32_t a) {
    asm volatile("ldmatrix.sync.aligned.m8n8.x4.shared.b16 {%0,%1,%2,%3}, [%4];"
        : "=r"(r[0]), "=r"(r[1]), "=r"(r[2]), "=r"(r[3]) : "r"(a));
}
__device__ __forceinline__ void mma_bf16(float* c, const uint32_t* a, uint32_t b0, uint32_t b1) {
    asm volatile(
        "mma.sync.aligned.m16n8k16.row.col.f32.bf16.bf16.f32 "
        "{%0,%1,%2,%3},{%4,%5,%6,%7},{%8,%9},{%0,%1,%2,%3};"
        : "+f"(c[0]), "+f"(c[1]), "+f"(c[2]), "+f"(c[3])
        : "r"(a[0]), "r"(a[1]), "r"(a[2]), "r"(a[3]), "r"(b0), "r"(b1));
}

// ======================= generic bf16 GEMM (stages 1,2,3,7) =======================
// 128x128x(BK=64) tile, 8 warps (2m x 4n), 3-stage cp.async.
__global__ __launch_bounds__(256) void gemm_bf16_kernel(
    const bf16* __restrict__ A, const bf16* __restrict__ B, void* __restrict__ Out,
    int K, int as, long aB, int bs, long bB, long oB, int ldO,
    int transOut, int outBf16, float alpha)
{
    extern __shared__ char smem[];
    const uint32_t sb = smem_u32(smem);
    const int tid = threadIdx.x, warp = tid >> 5, lane = tid & 31;
    const int m0 = blockIdx.x * 128, n0 = blockIdx.y * 128;
    const bf16* Ab = A + (long)blockIdx.z * aB + (long)m0 * as;
    const bf16* Bb = B + (long)blockIdx.z * bB + (long)n0 * bs;

    int crow[4], ckc[4]; uint32_t cdst[4];
    #pragma unroll
    for (int j = 0; j < 4; j++) {
        int idx = tid + j * 256;
        crow[j] = idx >> 3; ckc[j] = idx & 7;
        cdst[j] = SWZ((uint32_t)(crow[j] * 128 + ckc[j] * 16));
    }
    const int nk = K >> 6;

    #define ISSUE(IT) do {                                                    \
        int _kt = (IT) * 64;                                                  \
        uint32_t _sA = sb + ((IT) % 3) * 32768, _sB = _sA + 16384;            \
        _Pragma("unroll")                                                     \
        for (int j = 0; j < 4; j++) {                                         \
            cp16(_sA + cdst[j], Ab + (long)crow[j] * as + _kt + ckc[j] * 8);  \
            cp16(_sB + cdst[j], Bb + (long)crow[j] * bs + _kt + ckc[j] * 8);  \
        }                                                                     \
    } while (0)

    #pragma unroll
    for (int s = 0; s < 2; s++) {
        if (s < nk) ISSUE(s);
        asm volatile("cp.async.commit_group;" ::: "memory");
    }

    float acc[4][4][4];
    #pragma unroll
    for (int i = 0; i < 4; i++)
        #pragma unroll
        for (int j = 0; j < 4; j++)
            #pragma unroll
            for (int r = 0; r < 4; r++) acc[i][j][r] = 0.0f;

    const int wm = warp & 1, wn = warp >> 1;
    const int arow = lane & 15;
    const int ksel = (lane >> 4) * 16;

    for (int it = 0; it < nk; it++) {
        if (it + 2 < nk) ISSUE(it + 2);
        asm volatile("cp.async.commit_group;" ::: "memory");
        asm volatile("cp.async.wait_group 2;" ::: "memory");
        __syncthreads();

        const uint32_t sA = sb + (it % 3) * 32768, sB = sA + 16384;
        #pragma unroll
        for (int ks = 0; ks < 64; ks += 16) {
            uint32_t af[4][4], bfr[2][4];
            #pragma unroll
            for (int mt = 0; mt < 4; mt++)
                ldsm4(af[mt], sA + SWZ((uint32_t)((wm * 64 + mt * 16 + arow) * 128 + ks * 2 + ksel)));
            #pragma unroll
            for (int h = 0; h < 2; h++)
                ldsm4(bfr[h], sB + SWZ((uint32_t)((wn * 32 + h * 16 + arow) * 128 + ks * 2 + ksel)));
            #pragma unroll
            for (int mt = 0; mt < 4; mt++)
                #pragma unroll
                for (int nt = 0; nt < 4; nt++)
                    mma_bf16(acc[mt][nt], af[mt],
                             bfr[nt >> 1][nt & 1], bfr[nt >> 1][(nt & 1) + 2]);
        }
        __syncthreads();
    }

    const int gid = lane >> 2, tg = lane & 3;
    const long zo = (long)blockIdx.z * oB;
    #pragma unroll
    for (int mt = 0; mt < 4; mt++) {
        const int row = m0 + wm * 64 + mt * 16 + gid;
        #pragma unroll
        for (int nt = 0; nt < 4; nt++) {
            const int col = n0 + wn * 32 + nt * 8 + tg * 2;
            float v0 = acc[mt][nt][0] * alpha, v1 = acc[mt][nt][1] * alpha;
            float v2 = acc[mt][nt][2] * alpha, v3 = acc[mt][nt][3] * alpha;
            if (transOut) {
                bf16* O = (bf16*)Out + zo;
                O[(long)col * ldO + row]           = __float2bfloat16(v0);
                O[(long)(col + 1) * ldO + row]     = __float2bfloat16(v1);
                O[(long)col * ldO + row + 8]       = __float2bfloat16(v2);
                O[(long)(col + 1) * ldO + row + 8] = __float2bfloat16(v3);
            } else if (outBf16) {
                bf16* O = (bf16*)Out + zo;
                *(__nv_bfloat162*)&O[(long)row * ldO + col]       = __floats2bfloat162_rn(v0, v1);
                *(__nv_bfloat162*)&O[(long)(row + 8) * ldO + col] = __floats2bfloat162_rn(v2, v3);
            } else {
                float* O = (float*)Out + zo;
                *(float2*)&O[(long)row * ldO + col]       = make_float2(v0, v1);
                *(float2*)&O[(long)(row + 8) * ldO + col] = make_float2(v2, v3);
            }
        }
    }
}

// ======================= fused flash kernel (stages 4,5,6) =======================
// Br=64 q rows per CTA, Bc=64 kv per iter, 16 iters, E=256.
// smem: theta 32K | kv buf0 (phi 32K + gv 32K) | kv buf1 | P 8K | stats 1K
#define FL_KV0  32768
#define FL_KV1  98304
#define FL_P    163840
#define FL_PMAX 172032
#define FL_PSUM 172544
#define FL_TOTAL 173056

__global__ __launch_bounds__(256) void flash_kernel(
    const bf16* __restrict__ Th, const bf16* __restrict__ Ph,
    const bf16* __restrict__ Gv, bf16* __restrict__ Ob)
{
    extern __shared__ char smem[];
    const uint32_t sb = smem_u32(smem);
    const int tid = threadIdx.x, warp = tid >> 5, lane = tid & 31;
    const int WM = warp >> 1, WN = warp & 1;       // 4 m-warps x 2 n-warps
    const int gid = lane >> 2, tg = lane & 3;
    const int arow = lane & 15, ksel = (lane >> 4) * 16;
    const int q0 = blockIdx.x * 64, z = blockIdx.y;

    const bf16* ThB = Th + ((long)z * 4096 + q0) * 256;
    const bf16* PhB = Ph + (long)z * 1024 * 256;
    const bf16* GvB = Gv + (long)z * 256 * 1024;

    auto issue_kv = [&](int jj, uint32_t kvbase) {
        const bf16* ph = PhB + jj * 64 * 256;
        #pragma unroll
        for (int j = 0; j < 8; j++) {
            int i = tid + j * 256, row = i >> 5, c16 = i & 31;
            cp16(kvbase + (c16 >> 3) * 8192 + SWZ((uint32_t)(row * 128 + (c16 & 7) * 16)),
                 ph + row * 256 + c16 * 8);
        }
        const bf16* gvp = GvB + jj * 64;
        #pragma unroll
        for (int j = 0; j < 8; j++) {
            int i = tid + j * 256, e = i >> 3, cw = i & 7;
            cp16(kvbase + 32768 + SWZ((uint32_t)(e * 128 + cw * 16)),
                 gvp + e * 1024 + cw * 8);
        }
    };

    // prologue: theta tile (4 slabs of 64 rows x 64k) + kv tile 0
    #pragma unroll
    for (int j = 0; j < 8; j++) {
        int i = tid + j * 256, row = i >> 5, c16 = i & 31;
        cp16(sb + (c16 >> 3) * 8192 + SWZ((uint32_t)(row * 128 + (c16 & 7) * 16)),
             ThB + row * 256 + c16 * 8);
    }
    issue_kv(0, sb + FL_KV0);
    asm volatile("cp.async.commit_group;" ::: "memory");

    float m_lo = -1e30f, m_hi = -1e30f, l_lo = 0.0f, l_hi = 0.0f;
    float acc_o[16][4];
    #pragma unroll
    for (int i = 0; i < 16; i++)
        #pragma unroll
        for (int r = 0; r < 4; r++) acc_o[i][r] = 0.0f;

    const int rlo = WM * 16 + gid, rhi = rlo + 8;
    float* pmax = (float*)(smem + FL_PMAX);
    float* psum = (float*)(smem + FL_PSUM);

    for (int it = 0; it < 16; it++) {
        const uint32_t kvcur = sb + ((it & 1) ? FL_KV1 : FL_KV0);
        if (it + 1 < 16)
            issue_kv(it + 1, sb + (((it + 1) & 1) ? FL_KV1 : FL_KV0));
        asm volatile("cp.async.commit_group;" ::: "memory");
        asm volatile("cp.async.wait_group 1;" ::: "memory");
        __syncthreads();

        // ---- S = theta' . phi^T  (64x64, K=256) ----
        float s[4][4];
        #pragma unroll
        for (int i = 0; i < 4; i++)
            #pragma unroll
            for (int r = 0; r < 4; r++) s[i][r] = 0.0f;

        #pragma unroll
        for (int slab = 0; slab < 4; slab++) {
            const uint32_t thS = sb + slab * 8192;
            const uint32_t phS = kvcur + slab * 8192;
            #pragma unroll
            for (int ks = 0; ks < 4; ks++) {
                uint32_t af[4], bfr[2][4];
                ldsm4(af, thS + SWZ((uint32_t)((WM * 16 + arow) * 128 + ks * 32 + ksel)));
                ldsm4(bfr[0], phS + SWZ((uint32_t)((WN * 32 + arow) * 128 + ks * 32 + ksel)));
                ldsm4(bfr[1], phS + SWZ((uint32_t)((WN * 32 + 16 + arow) * 128 + ks * 32 + ksel)));
                #pragma unroll
                for (int nt = 0; nt < 4; nt++)
                    mma_bf16(s[nt], af, bfr[nt >> 1][nt & 1], bfr[nt >> 1][(nt & 1) + 2]);
            }
        }

        // ---- online softmax ----
        float vlo = -1e30f, vhi = -1e30f;
        #pragma unroll
        for (int nt = 0; nt < 4; nt++) {
            vlo = fmaxf(vlo, fmaxf(s[nt][0], s[nt][1]));
            vhi = fmaxf(vhi, fmaxf(s[nt][2], s[nt][3]));
        }
        vlo = fmaxf(vlo, __shfl_xor_sync(0xffffffffu, vlo, 1));
        vlo = fmaxf(vlo, __shfl_xor_sync(0xffffffffu, vlo, 2));
        vhi = fmaxf(vhi, __shfl_xor_sync(0xffffffffu, vhi, 1));
        vhi = fmaxf(vhi, __shfl_xor_sync(0xffffffffu, vhi, 2));
        if (tg == 0) { pmax[WN * 64 + rlo] = vlo; pmax[WN * 64 + rhi] = vhi; }
        __syncthreads();
        const float rmlo = fmaxf(pmax[rlo], pmax[64 + rlo]);
        const float rmhi = fmaxf(pmax[rhi], pmax[64 + rhi]);
        const float mnlo = fmaxf(m_lo, rmlo), mnhi = fmaxf(m_hi, rmhi);
        const float clo = __expf(m_lo - mnlo), chi = __expf(m_hi - mnhi);
        m_lo = mnlo; m_hi = mnhi;

        float slo = 0.0f, shi = 0.0f;
        #pragma unroll
        for (int nt = 0; nt < 4; nt++) {
            s[nt][0] = __expf(s[nt][0] - mnlo); s[nt][1] = __expf(s[nt][1] - mnlo);
            s[nt][2] = __expf(s[nt][2] - mnhi); s[nt][3] = __expf(s[nt][3] - mnhi);
            slo += s[nt][0] + s[nt][1];
            shi += s[nt][2] + s[nt][3];
        }
        slo += __shfl_xor_sync(0xffffffffu, slo, 1);
        slo += __shfl_xor_sync(0xffffffffu, slo, 2);
        shi += __shfl_xor_sync(0xffffffffu, shi, 1);
        shi += __shfl_xor_sync(0xffffffffu, shi, 2);
        if (tg == 0) { psum[WN * 64 + rlo] = slo; psum[WN * 64 + rhi] = shi; }
        __syncthreads();
        l_lo = l_lo * clo + psum[rlo] + psum[64 + rlo];
        l_hi = l_hi * chi + psum[rhi] + psum[64 + rhi];

        #pragma unroll
        for (int nt = 0; nt < 16; nt++) {
            acc_o[nt][0] *= clo; acc_o[nt][1] *= clo;
            acc_o[nt][2] *= chi; acc_o[nt][3] *= chi;
        }

        // write P tile (64x64 bf16, swizzled)
        char* Pp = smem + FL_P;
        #pragma unroll
        for (int nt = 0; nt < 4; nt++) {
            const int col = WN * 32 + nt * 8 + tg * 2;
            *(__nv_bfloat162*)(Pp + SWZ((uint32_t)(rlo * 128 + col * 2))) =
                __floats2bfloat162_rn(s[nt][0], s[nt][1]);
            *(__nv_bfloat162*)(Pp + SWZ((uint32_t)(rhi * 128 + col * 2))) =
                __floats2bfloat162_rn(s[nt][2], s[nt][3]);
        }
        __syncthreads();

        // ---- O += P . gv^T  (64 x 256, K=64) ----
        const uint32_t gvS = kvcur + 32768;
        const uint32_t pS = sb + FL_P;
        #pragma unroll
        for (int ks = 0; ks < 4; ks++) {
            uint32_t pf[4], gf[8][4];
            ldsm4(pf, pS + SWZ((uint32_t)((WM * 16 + arow) * 128 + ks * 32 + ksel)));
            #pragma unroll
            for (int h = 0; h < 8; h++)
                ldsm4(gf[h], gvS + SWZ((uint32_t)((WN * 128 + h * 16 + arow) * 128 + ks * 32 + ksel)));
            #pragma unroll
            for (int nt = 0; nt < 16; nt++)
                mma_bf16(acc_o[nt], pf, gf[nt >> 1][nt & 1], gf[nt >> 1][(nt & 1) + 2]);
        }
        __syncthreads();   // all reads of this kv buffer done before it is refilled
    }

    // epilogue: O / l -> bf16 obufT[q][e]
    const float ilo = 1.0f / l_lo, ihi = 1.0f / l_hi;
    bf16* Op = Ob + ((long)z * 4096 + q0) * 256;
    #pragma unroll
    for (int nt = 0; nt < 16; nt++) {
        const int e = WN * 128 + nt * 8 + tg * 2;
        *(__nv_bfloat162*)&Op[rlo * 256 + e] =
            __floats2bfloat162_rn(acc_o[nt][0] * ilo, acc_o[nt][1] * ilo);
        *(__nv_bfloat162*)&Op[rhi * 256 + e] =
            __floats2bfloat162_rn(acc_o[nt][2] * ihi, acc_o[nt][3] * ihi);
    }
}

// ============== transpose+convert (+ optional copy-through to out) ==============
// in f32 [Z][256][Cc] -> out bf16 [Z][Cc][256]; if copyDst, also copy raw f32
// to copyDst + z*(512*4096) + r*Cc + c  (the concat first half).
__global__ __launch_bounds__(256) void transcvt_kernel(
    const float* __restrict__ in, bf16* __restrict__ out,
    float* __restrict__ copyDst, int Cc)
{
    __shared__ float t[32][33];
    const long base = (long)blockIdx.z * 256 * Cc;
    const int c0 = blockIdx.x * 32, r0 = blockIdx.y * 32;
    const int tx = threadIdx.x, ty = threadIdx.y;
    #pragma unroll
    for (int i = 0; i < 4; i++) {
        float v = in[base + (long)(r0 + ty + i * 8) * Cc + c0 + tx];
        t[ty + i * 8][tx] = v;
        if (copyDst)
            copyDst[(long)blockIdx.z * (512L * 4096) + (long)(r0 + ty + i * 8) * Cc + c0 + tx] = v;
    }
    __syncthreads();
    #pragma unroll
    for (int i = 0; i < 4; i++)
        out[base + (long)(c0 + ty + i * 8) * 256 + r0 + tx] = __float2bfloat16(t[tx][ty + i * 8]);
}

__global__ __launch_bounds__(256) void cvt_kernel(
    const float* __restrict__ in, bf16* __restrict__ out)
{
    int i = blockIdx.x * 256 + threadIdx.x;
    out[i] = __float2bfloat16(in[i]);
}

extern "C" void kernel_launch(void* const* d_in, const int* in_sizes, int n_in,
                              void* d_out, int out_size)
{
    const float* C   = (const float*)d_in[0];
    const float* P   = (const float*)d_in[1];
    const float* thw = (const float*)d_in[2];
    const float* phw = (const float*)d_in[3];
    const float* gw  = (const float*)d_in[4];
    const float* ow  = (const float*)d_in[5];
    float* out = (float*)d_out;

    bf16 *w16, *CTb, *PTb, *thetaT, *phiT, *gv, *obufT;
    cudaGetSymbolAddress((void**)&w16, g_w16);
    cudaGetSymbolAddress((void**)&CTb, g_CTb);
    cudaGetSymbolAddress((void**)&PTb, g_PTb);
    cudaGetSymbolAddress((void**)&thetaT, g_thetaT);
    cudaGetSymbolAddress((void**)&phiT, g_phiT);
    cudaGetSymbolAddress((void**)&gv, g_gv);
    cudaGetSymbolAddress((void**)&obufT, g_obufT);

    static int attr_set = 0;
    if (!attr_set) {
        cudaFuncSetAttribute(gemm_bf16_kernel,
                             cudaFuncAttributeMaxDynamicSharedMemorySize, 98304);
        cudaFuncSetAttribute(flash_kernel,
                             cudaFuncAttributeMaxDynamicSharedMemorySize, FL_TOTAL);
        attr_set = 1;
    }

    const dim3 blk(256);
    const long NQ = 4096, NKV = 1024;

    // weights -> bf16 ; inputs -> transposed bf16 (C also copied into out half 1)
    cvt_kernel<<<256, blk>>>(thw, w16);
    cvt_kernel<<<256, blk>>>(phw, w16 + 65536);
    cvt_kernel<<<256, blk>>>(gw,  w16 + 2 * 65536);
    cvt_kernel<<<256, blk>>>(ow,  w16 + 3 * 65536);
    transcvt_kernel<<<dim3(128, 8, 8), dim3(32, 8)>>>(C, CTb, out, 4096);
    transcvt_kernel<<<dim3(32, 8, 8), dim3(32, 8)>>>(P, PTb, nullptr, 1024);

    // 1) thetaT[nq][e] = (thw @ C) / 16   (transposed bf16 out, scale folded)
    gemm_bf16_kernel<<<dim3(2, 32, 8), blk, 98304>>>(w16, CTb, thetaT, 256,
        256, 0, 256, NQ * 256, NQ * 256, 256, 1, 1, 0.0625f);
    // 2) phiT[nkv][e] = phw @ P
    gemm_bf16_kernel<<<dim3(2, 8, 8), blk, 98304>>>(w16 + 65536, PTb, phiT, 256,
        256, 0, 256, NKV * 256, NKV * 256, 256, 1, 1, 1.0f);
    // 3) gv[e][nkv] = gw @ P
    gemm_bf16_kernel<<<dim3(2, 8, 8), blk, 98304>>>(w16 + 2 * 65536, PTb, gv, 256,
        256, 0, 256, NKV * 256, 256 * NKV, 1024, 0, 1, 1.0f);
    // 4-6) fused attention: obufT[nq][e] = softmax(theta'.phi^T) . gv^T
    flash_kernel<<<dim3(64, 8), blk, FL_TOTAL>>>(thetaT, phiT, gv, obufT);
    // 7) out2[c][nq] = ow . obufT   (f32, second half of out)
    gemm_bf16_kernel<<<dim3(2, 32, 8), blk, 98304>>>(w16 + 3 * 65536, obufT,
        out + 256L * 4096, 256,
        256, 0, 256, NQ * 256, 512L * 4096, 4096, 0, 0, 1.0f);
}

// round 7
// speedup vs baseline: 2.6789x; 1.1001x over previous
#include <cuda_runtime.h>
#include <cuda_bf16.h>
#include <cstdint>

typedef __nv_bfloat16 bf16;

// ---------------------------------------------------------------------------
// CrossModalAttention, sm_100:
//   stages 1-3,7: bf16 m16n8k16 mma.sync GEMM (ldmatrix + cp.async, 3-stage)
//   stages 4-6  : fused flash kernel, theta-in-registers, pair barriers
// ---------------------------------------------------------------------------

__device__ bf16  g_w16   [4][65536];                 // thw, phw, gw, ow in bf16
__device__ bf16  g_CTb   [(size_t)8 * 4096 * 256];   // [B][Nq][CQ]
__device__ bf16  g_PTb   [(size_t)8 * 1024 * 256];   // [B][Nkv][CKV]
__device__ bf16  g_thetaT[(size_t)8 * 4096 * 256];   // [B][Nq][E] (pre-scaled 1/16)
__device__ bf16  g_phiT  [(size_t)8 * 1024 * 256];   // [B][Nkv][E]
__device__ bf16  g_gv    [(size_t)8 * 256 * 1024];   // [B][E][Nkv]
__device__ bf16  g_obufT [(size_t)8 * 4096 * 256];   // [B][Nq][E]

#define SWZ(x) ((x) ^ (((x) >> 3) & 0x70))

__device__ __forceinline__ uint32_t smem_u32(const void* p) {
    uint32_t a;
    asm("{ .reg .u64 t; cvta.to.shared.u64 t, %1; cvt.u32.u64 %0, t; }" : "=r"(a) : "l"(p));
    return a;
}
__device__ __forceinline__ void cp16(uint32_t dst, const void* src) {
    asm volatile("cp.async.cg.shared.global [%0], [%1], 16;" :: "r"(dst), "l"(src) : "memory");
}
__device__ __forceinline__ void ldsm4(uint32_t* r, uint32_t a) {
    asm volatile("ldmatrix.sync.aligned.m8n8.x4.shared.b16 {%0,%1,%2,%3}, [%4];"
        : "=r"(r[0]), "=r"(r[1]), "=r"(r[2]), "=r"(r[3]) : "r"(a));
}
__device__ __forceinline__ void mma_bf16(float* c, const uint32_t* a, uint32_t b0, uint32_t b1) {
    asm volatile(
        "mma.sync.aligned.m16n8k16.row.col.f32.bf16.bf16.f32 "
        "{%0,%1,%2,%3},{%4,%5,%6,%7},{%8,%9},{%0,%1,%2,%3};"
        : "+f"(c[0]), "+f"(c[1]), "+f"(c[2]), "+f"(c[3])
        : "r"(a[0]), "r"(a[1]), "r"(a[2]), "r"(a[3]), "r"(b0), "r"(b1));
}
__device__ __forceinline__ void bar_pair(int id) {
    asm volatile("bar.sync %0, 64;" :: "r"(id) : "memory");
}

// ======================= generic bf16 GEMM (stages 1,2,3,7) =======================
__global__ __launch_bounds__(256) void gemm_bf16_kernel(
    const bf16* __restrict__ A, const bf16* __restrict__ B, void* __restrict__ Out,
    int K, int as, long aB, int bs, long bB, long oB, int ldO,
    int transOut, int outBf16, float alpha)
{
    extern __shared__ char smem[];
    const uint32_t sb = smem_u32(smem);
    const int tid = threadIdx.x, warp = tid >> 5, lane = tid & 31;
    const int m0 = blockIdx.x * 128, n0 = blockIdx.y * 128;
    const bf16* Ab = A + (long)blockIdx.z * aB + (long)m0 * as;
    const bf16* Bb = B + (long)blockIdx.z * bB + (long)n0 * bs;

    int crow[4], ckc[4]; uint32_t cdst[4];
    #pragma unroll
    for (int j = 0; j < 4; j++) {
        int idx = tid + j * 256;
        crow[j] = idx >> 3; ckc[j] = idx & 7;
        cdst[j] = SWZ((uint32_t)(crow[j] * 128 + ckc[j] * 16));
    }
    const int nk = K >> 6;

    #define ISSUE(IT) do {                                                    \
        int _kt = (IT) * 64;                                                  \
        uint32_t _sA = sb + ((IT) % 3) * 32768, _sB = _sA + 16384;            \
        _Pragma("unroll")                                                     \
        for (int j = 0; j < 4; j++) {                                         \
            cp16(_sA + cdst[j], Ab + (long)crow[j] * as + _kt + ckc[j] * 8);  \
            cp16(_sB + cdst[j], Bb + (long)crow[j] * bs + _kt + ckc[j] * 8);  \
        }                                                                     \
    } while (0)

    #pragma unroll
    for (int s = 0; s < 2; s++) {
        if (s < nk) ISSUE(s);
        asm volatile("cp.async.commit_group;" ::: "memory");
    }

    float acc[4][4][4];
    #pragma unroll
    for (int i = 0; i < 4; i++)
        #pragma unroll
        for (int j = 0; j < 4; j++)
            #pragma unroll
            for (int r = 0; r < 4; r++) acc[i][j][r] = 0.0f;

    const int wm = warp & 1, wn = warp >> 1;
    const int arow = lane & 15;
    const int ksel = (lane >> 4) * 16;

    for (int it = 0; it < nk; it++) {
        if (it + 2 < nk) ISSUE(it + 2);
        asm volatile("cp.async.commit_group;" ::: "memory");
        asm volatile("cp.async.wait_group 2;" ::: "memory");
        __syncthreads();

        const uint32_t sA = sb + (it % 3) * 32768, sB = sA + 16384;
        #pragma unroll
        for (int ks = 0; ks < 64; ks += 16) {
            uint32_t af[4][4], bfr[2][4];
            #pragma unroll
            for (int mt = 0; mt < 4; mt++)
                ldsm4(af[mt], sA + SWZ((uint32_t)((wm * 64 + mt * 16 + arow) * 128 + ks * 2 + ksel)));
            #pragma unroll
            for (int h = 0; h < 2; h++)
                ldsm4(bfr[h], sB + SWZ((uint32_t)((wn * 32 + h * 16 + arow) * 128 + ks * 2 + ksel)));
            #pragma unroll
            for (int mt = 0; mt < 4; mt++)
                #pragma unroll
                for (int nt = 0; nt < 4; nt++)
                    mma_bf16(acc[mt][nt], af[mt],
                             bfr[nt >> 1][nt & 1], bfr[nt >> 1][(nt & 1) + 2]);
        }
        __syncthreads();
    }

    const int gid = lane >> 2, tg = lane & 3;
    const long zo = (long)blockIdx.z * oB;
    #pragma unroll
    for (int mt = 0; mt < 4; mt++) {
        const int row = m0 + wm * 64 + mt * 16 + gid;
        #pragma unroll
        for (int nt = 0; nt < 4; nt++) {
            const int col = n0 + wn * 32 + nt * 8 + tg * 2;
            float v0 = acc[mt][nt][0] * alpha, v1 = acc[mt][nt][1] * alpha;
            float v2 = acc[mt][nt][2] * alpha, v3 = acc[mt][nt][3] * alpha;
            if (transOut) {
                bf16* O = (bf16*)Out + zo;
                O[(long)col * ldO + row]           = __float2bfloat16(v0);
                O[(long)(col + 1) * ldO + row]     = __float2bfloat16(v1);
                O[(long)col * ldO + row + 8]       = __float2bfloat16(v2);
                O[(long)(col + 1) * ldO + row + 8] = __float2bfloat16(v3);
            } else if (outBf16) {
                bf16* O = (bf16*)Out + zo;
                *(__nv_bfloat162*)&O[(long)row * ldO + col]       = __floats2bfloat162_rn(v0, v1);
                *(__nv_bfloat162*)&O[(long)(row + 8) * ldO + col] = __floats2bfloat162_rn(v2, v3);
            } else {
                float* O = (float*)Out + zo;
                *(float2*)&O[(long)row * ldO + col]       = make_float2(v0, v1);
                *(float2*)&O[(long)(row + 8) * ldO + col] = make_float2(v2, v3);
            }
        }
    }
}

// ======================= fused flash kernel (stages 4,5,6) =======================
// smem: [0,32K) theta staging -> reused as P (8K) ; kv0 32K..96K ; kv1 96K..160K ;
//       stats at 160K. Theta fragments live in registers after prologue.
#define FL_KV0   32768
#define FL_KV1   98304
#define FL_STATS 163840
#define FL_TOTAL 164864

__global__ __launch_bounds__(256) void flash_kernel(
    const bf16* __restrict__ Th, const bf16* __restrict__ Ph,
    const bf16* __restrict__ Gv, bf16* __restrict__ Ob)
{
    extern __shared__ char smem[];
    const uint32_t sb = smem_u32(smem);
    const int tid = threadIdx.x, warp = tid >> 5, lane = tid & 31;
    const int WM = warp >> 1, WN = warp & 1;
    const int gid = lane >> 2, tg = lane & 3;
    const int arow = lane & 15, ksel = (lane >> 4) * 16;
    const int q0 = blockIdx.x * 64, z = blockIdx.y;

    const bf16* ThB = Th + ((long)z * 4096 + q0) * 256;
    const bf16* PhB = Ph + (long)z * 1024 * 256;
    const bf16* GvB = Gv + (long)z * 256 * 1024;

    auto issue_kv = [&](int jj, uint32_t kvbase) {
        const bf16* ph = PhB + jj * 64 * 256;
        #pragma unroll
        for (int j = 0; j < 8; j++) {
            int i = tid + j * 256, row = i >> 5, c16 = i & 31;
            cp16(kvbase + (c16 >> 3) * 8192 + SWZ((uint32_t)(row * 128 + (c16 & 7) * 16)),
                 ph + row * 256 + c16 * 8);
        }
        const bf16* gvp = GvB + jj * 64;
        #pragma unroll
        for (int j = 0; j < 8; j++) {
            int i = tid + j * 256, e = i >> 3, cw = i & 7;
            cp16(kvbase + 32768 + SWZ((uint32_t)(e * 128 + cw * 16)),
                 gvp + e * 1024 + cw * 8);
        }
    };

    // prologue: theta + kv0 (group 0), kv1 (group 1)
    #pragma unroll
    for (int j = 0; j < 8; j++) {
        int i = tid + j * 256, row = i >> 5, c16 = i & 31;
        cp16(sb + (c16 >> 3) * 8192 + SWZ((uint32_t)(row * 128 + (c16 & 7) * 16)),
             ThB + row * 256 + c16 * 8);
    }
    issue_kv(0, sb + FL_KV0);
    asm volatile("cp.async.commit_group;" ::: "memory");
    issue_kv(1, sb + FL_KV1);
    asm volatile("cp.async.commit_group;" ::: "memory");

    // theta -> registers (64 regs/thread), then free the staging region
    asm volatile("cp.async.wait_group 1;" ::: "memory");
    __syncthreads();
    uint32_t af_all[4][4][4];
    #pragma unroll
    for (int slab = 0; slab < 4; slab++)
        #pragma unroll
        for (int ks = 0; ks < 4; ks++)
            ldsm4(af_all[slab][ks],
                  sb + slab * 8192 + SWZ((uint32_t)((WM * 16 + arow) * 128 + ks * 32 + ksel)));
    __syncthreads();   // staging now reusable as P

    float m_lo = -1e30f, m_hi = -1e30f, l_lo = 0.0f, l_hi = 0.0f;
    float acc_o[16][4];
    #pragma unroll
    for (int i = 0; i < 16; i++)
        #pragma unroll
        for (int r = 0; r < 4; r++) acc_o[i][r] = 0.0f;

    const int rlo = WM * 16 + gid, rhi = rlo + 8;
    float* pmax = (float*)(smem + FL_STATS);
    float* psum = (float*)(smem + FL_STATS + 512);
    const int barid = WM + 1;

    for (int it = 0; it < 16; it++) {
        const uint32_t kvcur = sb + ((it & 1) ? FL_KV1 : FL_KV0);

        // ---- S = theta . phi^T  (64x64, K=256) ----
        float s[4][4];
        #pragma unroll
        for (int i = 0; i < 4; i++)
            #pragma unroll
            for (int r = 0; r < 4; r++) s[i][r] = 0.0f;
        #pragma unroll
        for (int slab = 0; slab < 4; slab++) {
            const uint32_t phS = kvcur + slab * 8192;
            #pragma unroll
            for (int ks = 0; ks < 4; ks++) {
                uint32_t bfr[2][4];
                ldsm4(bfr[0], phS + SWZ((uint32_t)((WN * 32 + arow) * 128 + ks * 32 + ksel)));
                ldsm4(bfr[1], phS + SWZ((uint32_t)((WN * 32 + 16 + arow) * 128 + ks * 32 + ksel)));
                #pragma unroll
                for (int nt = 0; nt < 4; nt++)
                    mma_bf16(s[nt], af_all[slab][ks],
                             bfr[nt >> 1][nt & 1], bfr[nt >> 1][(nt & 1) + 2]);
            }
        }

        // ---- online softmax (pair-scoped reductions) ----
        float vlo = -1e30f, vhi = -1e30f;
        #pragma unroll
        for (int nt = 0; nt < 4; nt++) {
            vlo = fmaxf(vlo, fmaxf(s[nt][0], s[nt][1]));
            vhi = fmaxf(vhi, fmaxf(s[nt][2], s[nt][3]));
        }
        vlo = fmaxf(vlo, __shfl_xor_sync(0xffffffffu, vlo, 1));
        vlo = fmaxf(vlo, __shfl_xor_sync(0xffffffffu, vlo, 2));
        vhi = fmaxf(vhi, __shfl_xor_sync(0xffffffffu, vhi, 1));
        vhi = fmaxf(vhi, __shfl_xor_sync(0xffffffffu, vhi, 2));
        if (tg == 0) { pmax[WN * 64 + rlo] = vlo; pmax[WN * 64 + rhi] = vhi; }
        bar_pair(barid);
        const float mnlo = fmaxf(m_lo, fmaxf(pmax[rlo], pmax[64 + rlo]));
        const float mnhi = fmaxf(m_hi, fmaxf(pmax[rhi], pmax[64 + rhi]));
        const float clo = __expf(m_lo - mnlo), chi = __expf(m_hi - mnhi);
        m_lo = mnlo; m_hi = mnhi;

        float slo = 0.0f, shi = 0.0f;
        #pragma unroll
        for (int nt = 0; nt < 4; nt++) {
            s[nt][0] = __expf(s[nt][0] - mnlo); s[nt][1] = __expf(s[nt][1] - mnlo);
            s[nt][2] = __expf(s[nt][2] - mnhi); s[nt][3] = __expf(s[nt][3] - mnhi);
            slo += s[nt][0] + s[nt][1];
            shi += s[nt][2] + s[nt][3];
        }
        l_lo = l_lo * clo + slo;          // deferred: per-thread partial sum
        l_hi = l_hi * chi + shi;

        #pragma unroll
        for (int nt = 0; nt < 16; nt++) {
            acc_o[nt][0] *= clo; acc_o[nt][1] *= clo;
            acc_o[nt][2] *= chi; acc_o[nt][3] *= chi;
        }

        // P tile (rows of this pair only) into reused staging region
        #pragma unroll
        for (int nt = 0; nt < 4; nt++) {
            const int col = WN * 32 + nt * 8 + tg * 2;
            *(__nv_bfloat162*)(smem + SWZ((uint32_t)(rlo * 128 + col * 2))) =
                __floats2bfloat162_rn(s[nt][0], s[nt][1]);
            *(__nv_bfloat162*)(smem + SWZ((uint32_t)(rhi * 128 + col * 2))) =
                __floats2bfloat162_rn(s[nt][2], s[nt][3]);
        }
        bar_pair(barid);

        // ---- O += P . gv^T  (64 x 256, K=64) ----
        const uint32_t gvS = kvcur + 32768;
        #pragma unroll
        for (int ks = 0; ks < 4; ks++) {
            uint32_t pf[4];
            ldsm4(pf, sb + SWZ((uint32_t)((WM * 16 + arow) * 128 + ks * 32 + ksel)));
            #pragma unroll
            for (int h = 0; h < 8; h++) {
                uint32_t gf[4];
                ldsm4(gf, gvS + SWZ((uint32_t)((WN * 128 + h * 16 + arow) * 128 + ks * 32 + ksel)));
                mma_bf16(acc_o[2 * h],     pf, gf[0], gf[2]);
                mma_bf16(acc_o[2 * h + 1], pf, gf[1], gf[3]);
            }
        }
        __syncthreads();                       // all reads of kvcur & P done
        if (it + 2 < 16) {
            issue_kv(it + 2, kvcur);           // refill the buffer just drained
            asm volatile("cp.async.commit_group;" ::: "memory");
            asm volatile("cp.async.wait_group 1;" ::: "memory");
            __syncthreads();                   // next buffer ready
        } else if (it + 1 < 16) {
            asm volatile("cp.async.wait_group 0;" ::: "memory");
            __syncthreads();
        }
    }

    // final l reduction: quad shfl + one pair exchange
    l_lo += __shfl_xor_sync(0xffffffffu, l_lo, 1);
    l_lo += __shfl_xor_sync(0xffffffffu, l_lo, 2);
    l_hi += __shfl_xor_sync(0xffffffffu, l_hi, 1);
    l_hi += __shfl_xor_sync(0xffffffffu, l_hi, 2);
    if (tg == 0) { psum[WN * 64 + rlo] = l_lo; psum[WN * 64 + rhi] = l_hi; }
    bar_pair(barid);
    const float ilo = 1.0f / (psum[rlo] + psum[64 + rlo]);
    const float ihi = 1.0f / (psum[rhi] + psum[64 + rhi]);

    bf16* Op = Ob + ((long)z * 4096 + q0) * 256;
    #pragma unroll
    for (int nt = 0; nt < 16; nt++) {
        const int e = WN * 128 + nt * 8 + tg * 2;
        *(__nv_bfloat162*)&Op[rlo * 256 + e] =
            __floats2bfloat162_rn(acc_o[nt][0] * ilo, acc_o[nt][1] * ilo);
        *(__nv_bfloat162*)&Op[rhi * 256 + e] =
            __floats2bfloat162_rn(acc_o[nt][2] * ihi, acc_o[nt][3] * ihi);
    }
}

// ============== transpose+convert (+ optional copy-through to out) ==============
__global__ __launch_bounds__(256) void transcvt_kernel(
    const float* __restrict__ in, bf16* __restrict__ out,
    float* __restrict__ copyDst, int Cc)
{
    __shared__ float t[32][33];
    const long base = (long)blockIdx.z * 256 * Cc;
    const int c0 = blockIdx.x * 32, r0 = blockIdx.y * 32;
    const int tx = threadIdx.x, ty = threadIdx.y;
    #pragma unroll
    for (int i = 0; i < 4; i++) {
        float v = in[base + (long)(r0 + ty + i * 8) * Cc + c0 + tx];
        t[ty + i * 8][tx] = v;
        if (copyDst)
            copyDst[(long)blockIdx.z * (512L * 4096) + (long)(r0 + ty + i * 8) * Cc + c0 + tx] = v;
    }
    __syncthreads();
    #pragma unroll
    for (int i = 0; i < 4; i++)
        out[base + (long)(c0 + ty + i * 8) * 256 + r0 + tx] = __float2bfloat16(t[tx][ty + i * 8]);
}

// all four 256x256 weights in one launch, float4-vectorized
__global__ __launch_bounds__(256) void cvt4_kernel(
    const float* __restrict__ a, const float* __restrict__ b,
    const float* __restrict__ c, const float* __restrict__ d,
    bf16* __restrict__ out)
{
    const float* srcs[4] = {a, b, c, d};
    int j = (blockIdx.x * 256 + threadIdx.x) * 4;     // 0..262140
    float4 v = *(const float4*)(srcs[j >> 16] + (j & 65535));
    *(__nv_bfloat162*)&out[j]     = __floats2bfloat162_rn(v.x, v.y);
    *(__nv_bfloat162*)&out[j + 2] = __floats2bfloat162_rn(v.z, v.w);
}

extern "C" void kernel_launch(void* const* d_in, const int* in_sizes, int n_in,
                              void* d_out, int out_size)
{
    const float* C   = (const float*)d_in[0];
    const float* P   = (const float*)d_in[1];
    const float* thw = (const float*)d_in[2];
    const float* phw = (const float*)d_in[3];
    const float* gw  = (const float*)d_in[4];
    const float* ow  = (const float*)d_in[5];
    float* out = (float*)d_out;

    bf16 *w16, *CTb, *PTb, *thetaT, *phiT, *gv, *obufT;
    cudaGetSymbolAddress((void**)&w16, g_w16);
    cudaGetSymbolAddress((void**)&CTb, g_CTb);
    cudaGetSymbolAddress((void**)&PTb, g_PTb);
    cudaGetSymbolAddress((void**)&thetaT, g_thetaT);
    cudaGetSymbolAddress((void**)&phiT, g_phiT);
    cudaGetSymbolAddress((void**)&gv, g_gv);
    cudaGetSymbolAddress((void**)&obufT, g_obufT);

    static int attr_set = 0;
    if (!attr_set) {
        cudaFuncSetAttribute(gemm_bf16_kernel,
                             cudaFuncAttributeMaxDynamicSharedMemorySize, 98304);
        cudaFuncSetAttribute(flash_kernel,
                             cudaFuncAttributeMaxDynamicSharedMemorySize, FL_TOTAL);
        attr_set = 1;
    }

    const dim3 blk(256);
    const long NQ = 4096, NKV = 1024;

    cvt4_kernel<<<256, blk>>>(thw, phw, gw, ow, w16);
    transcvt_kernel<<<dim3(128, 8, 8), dim3(32, 8)>>>(C, CTb, out, 4096);
    transcvt_kernel<<<dim3(32, 8, 8), dim3(32, 8)>>>(P, PTb, nullptr, 1024);

    // 1) thetaT[nq][e] = (thw @ C) / 16
    gemm_bf16_kernel<<<dim3(2, 32, 8), blk, 98304>>>(w16, CTb, thetaT, 256,
        256, 0, 256, NQ * 256, NQ * 256, 256, 1, 1, 0.0625f);
    // 2) phiT[nkv][e] = phw @ P
    gemm_bf16_kernel<<<dim3(2, 8, 8), blk, 98304>>>(w16 + 65536, PTb, phiT, 256,
        256, 0, 256, NKV * 256, NKV * 256, 256, 1, 1, 1.0f);
    // 3) gv[e][nkv] = gw @ P
    gemm_bf16_kernel<<<dim3(2, 8, 8), blk, 98304>>>(w16 + 2 * 65536, PTb, gv, 256,
        256, 0, 256, NKV * 256, 256 * NKV, 1024, 0, 1, 1.0f);
    // 4-6) fused attention
    flash_kernel<<<dim3(64, 8), blk, FL_TOTAL>>>(thetaT, phiT, gv, obufT);
    // 7) out2[c][nq] = ow . obufT
    gemm_bf16_kernel<<<dim3(2, 32, 8), blk, 98304>>>(w16 + 3 * 65536, obufT,
        out + 256L * 4096, 256,
        256, 0, 256, NQ * 256, 512L * 4096, 4096, 0, 0, 1.0f);
}

// round 8
// speedup vs baseline: 2.6810x; 1.0008x over previous
#include <cuda_runtime.h>
#include <cuda_bf16.h>
#include <cstdint>

typedef __nv_bfloat16 bf16;

// ---------------------------------------------------------------------------
// CrossModalAttention, sm_100:
//   stages 1-3,7: bf16 m16n8k16 mma.sync GEMM (ldmatrix + cp.async, 3-stage)
//   stages 4-6  : fused flash kernel, theta-in-registers, pair barriers
// ---------------------------------------------------------------------------

__device__ bf16  g_w16   [4][65536];                 // thw, phw, gw, ow in bf16
__device__ bf16  g_CTb   [(size_t)8 * 4096 * 256];   // [B][Nq][CQ]
__device__ bf16  g_PTb   [(size_t)8 * 1024 * 256];   // [B][Nkv][CKV]
__device__ bf16  g_thetaT[(size_t)8 * 4096 * 256];   // [B][Nq][E] (pre-scaled 1/16)
__device__ bf16  g_phiT  [(size_t)8 * 1024 * 256];   // [B][Nkv][E]
__device__ bf16  g_gv    [(size_t)8 * 256 * 1024];   // [B][E][Nkv]
__device__ bf16  g_obufT [(size_t)8 * 4096 * 256];   // [B][Nq][E]

#define SWZ(x) ((x) ^ (((x) >> 3) & 0x70))

__device__ __forceinline__ uint32_t smem_u32(const void* p) {
    uint32_t a;
    asm("{ .reg .u64 t; cvta.to.shared.u64 t, %1; cvt.u32.u64 %0, t; }" : "=r"(a) : "l"(p));
    return a;
}
__device__ __forceinline__ void cp16(uint32_t dst, const void* src) {
    asm volatile("cp.async.cg.shared.global [%0], [%1], 16;" :: "r"(dst), "l"(src) : "memory");
}
__device__ __forceinline__ void ldsm4(uint32_t* r, uint32_t a) {
    asm volatile("ldmatrix.sync.aligned.m8n8.x4.shared.b16 {%0,%1,%2,%3}, [%4];"
        : "=r"(r[0]), "=r"(r[1]), "=r"(r[2]), "=r"(r[3]) : "r"(a));
}
__device__ __forceinline__ void mma_bf16(float* c, const uint32_t* a, uint32_t b0, uint32_t b1) {
    asm volatile(
        "mma.sync.aligned.m16n8k16.row.col.f32.bf16.bf16.f32 "
        "{%0,%1,%2,%3},{%4,%5,%6,%7},{%8,%9},{%0,%1,%2,%3};"
        : "+f"(c[0]), "+f"(c[1]), "+f"(c[2]), "+f"(c[3])
        : "r"(a[0]), "r"(a[1]), "r"(a[2]), "r"(a[3]), "r"(b0), "r"(b1));
}
__device__ __forceinline__ void bar_pair(int id) {
    asm volatile("bar.sync %0, 64;" :: "r"(id) : "memory");
}

// ======================= generic bf16 GEMM (stages 1,2,3,7) =======================
__global__ __launch_bounds__(256) void gemm_bf16_kernel(
    const bf16* __restrict__ A, const bf16* __restrict__ B, void* __restrict__ Out,
    int K, int as, long aB, int bs, long bB, long oB, int ldO,
    int transOut, int outBf16, float alpha)
{
    extern __shared__ char smem[];
    const uint32_t sb = smem_u32(smem);
    const int tid = threadIdx.x, warp = tid >> 5, lane = tid & 31;
    const int m0 = blockIdx.x * 128, n0 = blockIdx.y * 128;
    const bf16* Ab = A + (long)blockIdx.z * aB + (long)m0 * as;
    const bf16* Bb = B + (long)blockIdx.z * bB + (long)n0 * bs;

    int crow[4], ckc[4]; uint32_t cdst[4];
    #pragma unroll
    for (int j = 0; j < 4; j++) {
        int idx = tid + j * 256;
        crow[j] = idx >> 3; ckc[j] = idx & 7;
        cdst[j] = SWZ((uint32_t)(crow[j] * 128 + ckc[j] * 16));
    }
    const int nk = K >> 6;

    #define ISSUE(IT) do {                                                    \
        int _kt = (IT) * 64;                                                  \
        uint32_t _sA = sb + ((IT) % 3) * 32768, _sB = _sA + 16384;            \
        _Pragma("unroll")                                                     \
        for (int j = 0; j < 4; j++) {                                         \
            cp16(_sA + cdst[j], Ab + (long)crow[j] * as + _kt + ckc[j] * 8);  \
            cp16(_sB + cdst[j], Bb + (long)crow[j] * bs + _kt + ckc[j] * 8);  \
        }                                                                     \
    } while (0)

    #pragma unroll
    for (int s = 0; s < 2; s++) {
        if (s < nk) ISSUE(s);
        asm volatile("cp.async.commit_group;" ::: "memory");
    }

    float acc[4][4][4];
    #pragma unroll
    for (int i = 0; i < 4; i++)
        #pragma unroll
        for (int j = 0; j < 4; j++)
            #pragma unroll
            for (int r = 0; r < 4; r++) acc[i][j][r] = 0.0f;

    const int wm = warp & 1, wn = warp >> 1;
    const int arow = lane & 15;
    const int ksel = (lane >> 4) * 16;

    for (int it = 0; it < nk; it++) {
        if (it + 2 < nk) ISSUE(it + 2);
        asm volatile("cp.async.commit_group;" ::: "memory");
        asm volatile("cp.async.wait_group 2;" ::: "memory");
        __syncthreads();

        const uint32_t sA = sb + (it % 3) * 32768, sB = sA + 16384;
        #pragma unroll
        for (int ks = 0; ks < 64; ks += 16) {
            uint32_t af[4][4], bfr[2][4];
            #pragma unroll
            for (int mt = 0; mt < 4; mt++)
                ldsm4(af[mt], sA + SWZ((uint32_t)((wm * 64 + mt * 16 + arow) * 128 + ks * 2 + ksel)));
            #pragma unroll
            for (int h = 0; h < 2; h++)
                ldsm4(bfr[h], sB + SWZ((uint32_t)((wn * 32 + h * 16 + arow) * 128 + ks * 2 + ksel)));
            #pragma unroll
            for (int mt = 0; mt < 4; mt++)
                #pragma unroll
                for (int nt = 0; nt < 4; nt++)
                    mma_bf16(acc[mt][nt], af[mt],
                             bfr[nt >> 1][nt & 1], bfr[nt >> 1][(nt & 1) + 2]);
        }
        __syncthreads();
    }

    const int gid = lane >> 2, tg = lane & 3;
    const long zo = (long)blockIdx.z * oB;
    #pragma unroll
    for (int mt = 0; mt < 4; mt++) {
        const int row = m0 + wm * 64 + mt * 16 + gid;
        #pragma unroll
        for (int nt = 0; nt < 4; nt++) {
            const int col = n0 + wn * 32 + nt * 8 + tg * 2;
            float v0 = acc[mt][nt][0] * alpha, v1 = acc[mt][nt][1] * alpha;
            float v2 = acc[mt][nt][2] * alpha, v3 = acc[mt][nt][3] * alpha;
            if (transOut) {
                bf16* O = (bf16*)Out + zo;
                O[(long)col * ldO + row]           = __float2bfloat16(v0);
                O[(long)(col + 1) * ldO + row]     = __float2bfloat16(v1);
                O[(long)col * ldO + row + 8]       = __float2bfloat16(v2);
                O[(long)(col + 1) * ldO + row + 8] = __float2bfloat16(v3);
            } else if (outBf16) {
                bf16* O = (bf16*)Out + zo;
                *(__nv_bfloat162*)&O[(long)row * ldO + col]       = __floats2bfloat162_rn(v0, v1);
                *(__nv_bfloat162*)&O[(long)(row + 8) * ldO + col] = __floats2bfloat162_rn(v2, v3);
            } else {
                float* O = (float*)Out + zo;
                *(float2*)&O[(long)row * ldO + col]       = make_float2(v0, v1);
                *(float2*)&O[(long)(row + 8) * ldO + col] = make_float2(v2, v3);
            }
        }
    }
}

// ======================= fused flash kernel (stages 4,5,6) =======================
// smem: [0,32K) theta staging -> reused as P (8K) ; kv0 32K..96K ; kv1 96K..160K ;
//       stats at 160K. Theta fragments live in registers after prologue.
#define FL_KV0   32768
#define FL_KV1   98304
#define FL_STATS 163840
#define FL_TOTAL 164864

__global__ __launch_bounds__(256) void flash_kernel(
    const bf16* __restrict__ Th, const bf16* __restrict__ Ph,
    const bf16* __restrict__ Gv, bf16* __restrict__ Ob)
{
    extern __shared__ char smem[];
    const uint32_t sb = smem_u32(smem);
    const int tid = threadIdx.x, warp = tid >> 5, lane = tid & 31;
    const int WM = warp >> 1, WN = warp & 1;
    const int gid = lane >> 2, tg = lane & 3;
    const int arow = lane & 15, ksel = (lane >> 4) * 16;
    const int q0 = blockIdx.x * 64, z = blockIdx.y;

    const bf16* ThB = Th + ((long)z * 4096 + q0) * 256;
    const bf16* PhB = Ph + (long)z * 1024 * 256;
    const bf16* GvB = Gv + (long)z * 256 * 1024;

    auto issue_kv = [&](int jj, uint32_t kvbase) {
        const bf16* ph = PhB + jj * 64 * 256;
        #pragma unroll
        for (int j = 0; j < 8; j++) {
            int i = tid + j * 256, row = i >> 5, c16 = i & 31;
            cp16(kvbase + (c16 >> 3) * 8192 + SWZ((uint32_t)(row * 128 + (c16 & 7) * 16)),
                 ph + row * 256 + c16 * 8);
        }
        const bf16* gvp = GvB + jj * 64;
        #pragma unroll
        for (int j = 0; j < 8; j++) {
            int i = tid + j * 256, e = i >> 3, cw = i & 7;
            cp16(kvbase + 32768 + SWZ((uint32_t)(e * 128 + cw * 16)),
                 gvp + e * 1024 + cw * 8);
        }
    };

    // prologue: theta + kv0 (group 0), kv1 (group 1)
    #pragma unroll
    for (int j = 0; j < 8; j++) {
        int i = tid + j * 256, row = i >> 5, c16 = i & 31;
        cp16(sb + (c16 >> 3) * 8192 + SWZ((uint32_t)(row * 128 + (c16 & 7) * 16)),
             ThB + row * 256 + c16 * 8);
    }
    issue_kv(0, sb + FL_KV0);
    asm volatile("cp.async.commit_group;" ::: "memory");
    issue_kv(1, sb + FL_KV1);
    asm volatile("cp.async.commit_group;" ::: "memory");

    // theta -> registers (64 regs/thread), then free the staging region
    asm volatile("cp.async.wait_group 1;" ::: "memory");
    __syncthreads();
    uint32_t af_all[4][4][4];
    #pragma unroll
    for (int slab = 0; slab < 4; slab++)
        #pragma unroll
        for (int ks = 0; ks < 4; ks++)
            ldsm4(af_all[slab][ks],
                  sb + slab * 8192 + SWZ((uint32_t)((WM * 16 + arow) * 128 + ks * 32 + ksel)));
    __syncthreads();   // staging now reusable as P

    float m_lo = -1e30f, m_hi = -1e30f, l_lo = 0.0f, l_hi = 0.0f;
    float acc_o[16][4];
    #pragma unroll
    for (int i = 0; i < 16; i++)
        #pragma unroll
        for (int r = 0; r < 4; r++) acc_o[i][r] = 0.0f;

    const int rlo = WM * 16 + gid, rhi = rlo + 8;
    float* pmax = (float*)(smem + FL_STATS);
    float* psum = (float*)(smem + FL_STATS + 512);
    const int barid = WM + 1;

    for (int it = 0; it < 16; it++) {
        const uint32_t kvcur = sb + ((it & 1) ? FL_KV1 : FL_KV0);

        // ---- S = theta . phi^T  (64x64, K=256) ----
        float s[4][4];
        #pragma unroll
        for (int i = 0; i < 4; i++)
            #pragma unroll
            for (int r = 0; r < 4; r++) s[i][r] = 0.0f;
        #pragma unroll
        for (int slab = 0; slab < 4; slab++) {
            const uint32_t phS = kvcur + slab * 8192;
            #pragma unroll
            for (int ks = 0; ks < 4; ks++) {
                uint32_t bfr[2][4];
                ldsm4(bfr[0], phS + SWZ((uint32_t)((WN * 32 + arow) * 128 + ks * 32 + ksel)));
                ldsm4(bfr[1], phS + SWZ((uint32_t)((WN * 32 + 16 + arow) * 128 + ks * 32 + ksel)));
                #pragma unroll
                for (int nt = 0; nt < 4; nt++)
                    mma_bf16(s[nt], af_all[slab][ks],
                             bfr[nt >> 1][nt & 1], bfr[nt >> 1][(nt & 1) + 2]);
            }
        }

        // ---- online softmax (pair-scoped reductions) ----
        float vlo = -1e30f, vhi = -1e30f;
        #pragma unroll
        for (int nt = 0; nt < 4; nt++) {
            vlo = fmaxf(vlo, fmaxf(s[nt][0], s[nt][1]));
            vhi = fmaxf(vhi, fmaxf(s[nt][2], s[nt][3]));
        }
        vlo = fmaxf(vlo, __shfl_xor_sync(0xffffffffu, vlo, 1));
        vlo = fmaxf(vlo, __shfl_xor_sync(0xffffffffu, vlo, 2));
        vhi = fmaxf(vhi, __shfl_xor_sync(0xffffffffu, vhi, 1));
        vhi = fmaxf(vhi, __shfl_xor_sync(0xffffffffu, vhi, 2));
        if (tg == 0) { pmax[WN * 64 + rlo] = vlo; pmax[WN * 64 + rhi] = vhi; }
        bar_pair(barid);
        const float mnlo = fmaxf(m_lo, fmaxf(pmax[rlo], pmax[64 + rlo]));
        const float mnhi = fmaxf(m_hi, fmaxf(pmax[rhi], pmax[64 + rhi]));
        const float clo = __expf(m_lo - mnlo), chi = __expf(m_hi - mnhi);
        m_lo = mnlo; m_hi = mnhi;

        float slo = 0.0f, shi = 0.0f;
        #pragma unroll
        for (int nt = 0; nt < 4; nt++) {
            s[nt][0] = __expf(s[nt][0] - mnlo); s[nt][1] = __expf(s[nt][1] - mnlo);
            s[nt][2] = __expf(s[nt][2] - mnhi); s[nt][3] = __expf(s[nt][3] - mnhi);
            slo += s[nt][0] + s[nt][1];
            shi += s[nt][2] + s[nt][3];
        }
        l_lo = l_lo * clo + slo;          // deferred: per-thread partial sum
        l_hi = l_hi * chi + shi;

        #pragma unroll
        for (int nt = 0; nt < 16; nt++) {
            acc_o[nt][0] *= clo; acc_o[nt][1] *= clo;
            acc_o[nt][2] *= chi; acc_o[nt][3] *= chi;
        }

        // P tile (rows of this pair only) into reused staging region
        #pragma unroll
        for (int nt = 0; nt < 4; nt++) {
            const int col = WN * 32 + nt * 8 + tg * 2;
            *(__nv_bfloat162*)(smem + SWZ((uint32_t)(rlo * 128 + col * 2))) =
                __floats2bfloat162_rn(s[nt][0], s[nt][1]);
            *(__nv_bfloat162*)(smem + SWZ((uint32_t)(rhi * 128 + col * 2))) =
                __floats2bfloat162_rn(s[nt][2], s[nt][3]);
        }
        bar_pair(barid);

        // ---- O += P . gv^T  (64 x 256, K=64) ----
        const uint32_t gvS = kvcur + 32768;
        #pragma unroll
        for (int ks = 0; ks < 4; ks++) {
            uint32_t pf[4];
            ldsm4(pf, sb + SWZ((uint32_t)((WM * 16 + arow) * 128 + ks * 32 + ksel)));
            #pragma unroll
            for (int h = 0; h < 8; h++) {
                uint32_t gf[4];
                ldsm4(gf, gvS + SWZ((uint32_t)((WN * 128 + h * 16 + arow) * 128 + ks * 32 + ksel)));
                mma_bf16(acc_o[2 * h],     pf, gf[0], gf[2]);
                mma_bf16(acc_o[2 * h + 1], pf, gf[1], gf[3]);
            }
        }
        __syncthreads();                       // all reads of kvcur & P done
        if (it + 2 < 16) {
            issue_kv(it + 2, kvcur);           // refill the buffer just drained
            asm volatile("cp.async.commit_group;" ::: "memory");
            asm volatile("cp.async.wait_group 1;" ::: "memory");
            __syncthreads();                   // next buffer ready
        } else if (it + 1 < 16) {
            asm volatile("cp.async.wait_group 0;" ::: "memory");
            __syncthreads();
        }
    }

    // final l reduction: quad shfl + one pair exchange
    l_lo += __shfl_xor_sync(0xffffffffu, l_lo, 1);
    l_lo += __shfl_xor_sync(0xffffffffu, l_lo, 2);
    l_hi += __shfl_xor_sync(0xffffffffu, l_hi, 1);
    l_hi += __shfl_xor_sync(0xffffffffu, l_hi, 2);
    if (tg == 0) { psum[WN * 64 + rlo] = l_lo; psum[WN * 64 + rhi] = l_hi; }
    bar_pair(barid);
    const float ilo = 1.0f / (psum[rlo] + psum[64 + rlo]);
    const float ihi = 1.0f / (psum[rhi] + psum[64 + rhi]);

    bf16* Op = Ob + ((long)z * 4096 + q0) * 256;
    #pragma unroll
    for (int nt = 0; nt < 16; nt++) {
        const int e = WN * 128 + nt * 8 + tg * 2;
        *(__nv_bfloat162*)&Op[rlo * 256 + e] =
            __floats2bfloat162_rn(acc_o[nt][0] * ilo, acc_o[nt][1] * ilo);
        *(__nv_bfloat162*)&Op[rhi * 256 + e] =
            __floats2bfloat162_rn(acc_o[nt][2] * ihi, acc_o[nt][3] * ihi);
    }
}

// ============== transpose+convert (+ optional copy-through to out) ==============
__global__ __launch_bounds__(256) void transcvt_kernel(
    const float* __restrict__ in, bf16* __restrict__ out,
    float* __restrict__ copyDst, int Cc)
{
    __shared__ float t[32][33];
    const long base = (long)blockIdx.z * 256 * Cc;
    const int c0 = blockIdx.x * 32, r0 = blockIdx.y * 32;
    const int tx = threadIdx.x, ty = threadIdx.y;
    #pragma unroll
    for (int i = 0; i < 4; i++) {
        float v = in[base + (long)(r0 + ty + i * 8) * Cc + c0 + tx];
        t[ty + i * 8][tx] = v;
        if (copyDst)
            copyDst[(long)blockIdx.z * (512L * 4096) + (long)(r0 + ty + i * 8) * Cc + c0 + tx] = v;
    }
    __syncthreads();
    #pragma unroll
    for (int i = 0; i < 4; i++)
        out[base + (long)(c0 + ty + i * 8) * 256 + r0 + tx] = __float2bfloat16(t[tx][ty + i * 8]);
}

// all four 256x256 weights in one launch, float4-vectorized
__global__ __launch_bounds__(256) void cvt4_kernel(
    const float* __restrict__ a, const float* __restrict__ b,
    const float* __restrict__ c, const float* __restrict__ d,
    bf16* __restrict__ out)
{
    const float* srcs[4] = {a, b, c, d};
    int j = (blockIdx.x * 256 + threadIdx.x) * 4;     // 0..262140
    float4 v = *(const float4*)(srcs[j >> 16] + (j & 65535));
    *(__nv_bfloat162*)&out[j]     = __floats2bfloat162_rn(v.x, v.y);
    *(__nv_bfloat162*)&out[j + 2] = __floats2bfloat162_rn(v.z, v.w);
}

extern "C" void kernel_launch(void* const* d_in, const int* in_sizes, int n_in,
                              void* d_out, int out_size)
{
    const float* C   = (const float*)d_in[0];
    const float* P   = (const float*)d_in[1];
    const float* thw = (const float*)d_in[2];
    const float* phw = (const float*)d_in[3];
    const float* gw  = (const float*)d_in[4];
    const float* ow  = (const float*)d_in[5];
    float* out = (float*)d_out;

    bf16 *w16, *CTb, *PTb, *thetaT, *phiT, *gv, *obufT;
    cudaGetSymbolAddress((void**)&w16, g_w16);
    cudaGetSymbolAddress((void**)&CTb, g_CTb);
    cudaGetSymbolAddress((void**)&PTb, g_PTb);
    cudaGetSymbolAddress((void**)&thetaT, g_thetaT);
    cudaGetSymbolAddress((void**)&phiT, g_phiT);
    cudaGetSymbolAddress((void**)&gv, g_gv);
    cudaGetSymbolAddress((void**)&obufT, g_obufT);

    static int attr_set = 0;
    if (!attr_set) {
        cudaFuncSetAttribute(gemm_bf16_kernel,
                             cudaFuncAttributeMaxDynamicSharedMemorySize, 98304);
        cudaFuncSetAttribute(flash_kernel,
                             cudaFuncAttributeMaxDynamicSharedMemorySize, FL_TOTAL);
        attr_set = 1;
    }

    const dim3 blk(256);
    const long NQ = 4096, NKV = 1024;

    cvt4_kernel<<<256, blk>>>(thw, phw, gw, ow, w16);
    transcvt_kernel<<<dim3(128, 8, 8), dim3(32, 8)>>>(C, CTb, out, 4096);
    transcvt_kernel<<<dim3(32, 8, 8), dim3(32, 8)>>>(P, PTb, nullptr, 1024);

    // 1) thetaT[nq][e] = (thw @ C) / 16
    gemm_bf16_kernel<<<dim3(2, 32, 8), blk, 98304>>>(w16, CTb, thetaT, 256,
        256, 0, 256, NQ * 256, NQ * 256, 256, 1, 1, 0.0625f);
    // 2) phiT[nkv][e] = phw @ P
    gemm_bf16_kernel<<<dim3(2, 8, 8), blk, 98304>>>(w16 + 65536, PTb, phiT, 256,
        256, 0, 256, NKV * 256, NKV * 256, 256, 1, 1, 1.0f);
    // 3) gv[e][nkv] = gw @ P
    gemm_bf16_kernel<<<dim3(2, 8, 8), blk, 98304>>>(w16 + 2 * 65536, PTb, gv, 256,
        256, 0, 256, NKV * 256, 256 * NKV, 1024, 0, 1, 1.0f);
    // 4-6) fused attention
    flash_kernel<<<dim3(64, 8), blk, FL_TOTAL>>>(thetaT, phiT, gv, obufT);
    // 7) out2[c][nq] = ow . obufT
    gemm_bf16_kernel<<<dim3(2, 32, 8), blk, 98304>>>(w16 + 3 * 65536, obufT,
        out + 256L * 4096, 256,
        256, 0, 256, NQ * 256, 512L * 4096, 4096, 0, 0, 1.0f);
}